// round 1
// baseline (speedup 1.0000x reference)
#include <cuda_runtime.h>
#include <cstdint>
#include <cstddef>

// Problem constants
#define B_   16
#define NPT  4096      // points in set 1 (per batch)
#define SPT  1024      // points in set 2 (per batch)
#define D1_  256
#define D2_  128
#define CIN  384       // D1 + D2
#define CO   256       // output channels of both conv layers
#define NS   (B_*NPT)  // 65536 samples for BN stats

// ---------------------------------------------------------------------------
// Scratch (device globals: allocation-free per harness rules)
// ---------------------------------------------------------------------------
__device__ float g_p2t[B_ * SPT * D2_];          //  8 MB: points2 transposed [B,S,D2]
__device__ float g_interp[B_ * D2_ * NPT];       // 32 MB: interpolated feats [B,D2,N]
__device__ float g_y1[B_ * CO * NPT];            // 64 MB: layer-1 pre-BN output
__device__ float g_alpha1[CO], g_beta1[CO];      // folded BN affine, layer 1
__device__ float g_alpha2[CO], g_beta2[CO];      // folded BN affine, layer 2

// ---------------------------------------------------------------------------
// Kernel 1: transpose points2 [B,D2,S] -> g_p2t [B,S,D2]  (coalesced both ways)
// ---------------------------------------------------------------------------
__global__ void k_transpose(const float* __restrict__ p2)
{
    __shared__ float t[32][33];
    const int b  = blockIdx.z;
    const int c0 = blockIdx.y * 32;
    const int s0 = blockIdx.x * 32;
    const int tx = threadIdx.x, ty = threadIdx.y;
#pragma unroll
    for (int i = 0; i < 4; i++) {
        int c = c0 + ty + i * 8;
        t[ty + i * 8][tx] = p2[((size_t)b * D2_ + c) * SPT + s0 + tx];
    }
    __syncthreads();
#pragma unroll
    for (int i = 0; i < 4; i++) {
        int s = s0 + ty + i * 8;
        g_p2t[((size_t)b * SPT + s) * D2_ + c0 + tx] = t[tx][ty + i * 8];
    }
}

// ---------------------------------------------------------------------------
// Kernel 2: 3-NN search + inverse-distance interpolation.
// One block = one batch x 128 query points. Phase 1: each thread scans all
// 1024 reference points (xyz2 staged in smem) keeping the 3 smallest d^2.
// Phase 2: each warp gathers contiguous 512B rows of g_p2t and accumulates
// the weighted sum into a padded smem tile. Phase 3: coalesced write of
// g_interp in [B,D2,N] layout.
// Dynamic smem: 3072 (xyz2) + 384 (w) + 384 (idx) + 128*129 (acc) floats.
// ---------------------------------------------------------------------------
#define INTERP_SMEM ((3072 + 384 + 384 + 128 * 129) * 4)

__global__ void __launch_bounds__(128) k_interp(const float* __restrict__ xyz1,
                                                const float* __restrict__ xyz2)
{
    extern __shared__ float sm[];
    float* x2s = sm;                       // [3][1024]
    float* wsh = sm + 3072;                // [128][3]
    int*   ish = (int*)(sm + 3072 + 384);  // [128][3]
    float* acc = sm + 3072 + 768;          // [128][129] (padded)

    const int b   = blockIdx.y;
    const int n0  = blockIdx.x * 128;
    const int tid = threadIdx.x;

    for (int i = tid; i < 3072; i += 128) x2s[i] = xyz2[(size_t)b * 3072 + i];
    __syncthreads();

    // ---- phase 1: top-3 nearest neighbors for point n0+tid ----
    {
        const int n = n0 + tid;
        const float px = xyz1[((size_t)b * 3 + 0) * NPT + n];
        const float py = xyz1[((size_t)b * 3 + 1) * NPT + n];
        const float pz = xyz1[((size_t)b * 3 + 2) * NPT + n];
        float d0 = 1e30f, d1 = 1e30f, d2 = 1e30f;
        int   i0 = 0,     i1 = 0,     i2 = 0;
#pragma unroll 4
        for (int s = 0; s < SPT; s++) {
            float dx = x2s[s]        - px;
            float dy = x2s[1024 + s] - py;
            float dz = x2s[2048 + s] - pz;
            float d  = fmaf(dx, dx, fmaf(dy, dy, dz * dz));
            if (d < d2) {
                if (d < d1) {
                    if (d < d0) { d2 = d1; i2 = i1; d1 = d0; i1 = i0; d0 = d; i0 = s; }
                    else        { d2 = d1; i2 = i1; d1 = d;  i1 = s; }
                } else          { d2 = d;  i2 = s; }
            }
        }
        float w0 = 1.f / (sqrtf(d0) + 1e-10f);
        float w1 = 1.f / (sqrtf(d1) + 1e-10f);
        float w2 = 1.f / (sqrtf(d2) + 1e-10f);
        float inv = 1.f / (w0 + w1 + w2);
        wsh[tid * 3 + 0] = w0 * inv; ish[tid * 3 + 0] = i0;
        wsh[tid * 3 + 1] = w1 * inv; ish[tid * 3 + 1] = i1;
        wsh[tid * 3 + 2] = w2 * inv; ish[tid * 3 + 2] = i2;
    }
    __syncthreads();

    // ---- phase 2: gather + weighted accumulate (warp per point, coalesced rows) ----
    {
        const int w = tid >> 5, l = tid & 31;
        const float* p2t = g_p2t + (size_t)b * SPT * D2_;
        for (int it = 0; it < 32; it++) {
            const int nl = w * 32 + it;
            float4 a = make_float4(0.f, 0.f, 0.f, 0.f);
#pragma unroll
            for (int k = 0; k < 3; k++) {
                const float wt = wsh[nl * 3 + k];
                const int   id = ish[nl * 3 + k];
                const float4 v = *reinterpret_cast<const float4*>(p2t + (size_t)id * D2_ + l * 4);
                a.x = fmaf(wt, v.x, a.x); a.y = fmaf(wt, v.y, a.y);
                a.z = fmaf(wt, v.z, a.z); a.w = fmaf(wt, v.w, a.w);
            }
            float* row = acc + nl * 129 + l * 4;
            row[0] = a.x; row[1] = a.y; row[2] = a.z; row[3] = a.w;
        }
    }
    __syncthreads();

    // ---- phase 3: coalesced write in [B,D2,N] layout ----
    float* dst = g_interp + ((size_t)b * D2_) * NPT + n0;
    for (int c = 0; c < D2_; c++)
        dst[(size_t)c * NPT + tid] = acc[tid * 129 + c];
}

// ---------------------------------------------------------------------------
// Kernel 3: SGEMM  y[o,s] = sum_c W[o,c] * x[c,s]  (+ bias in epilogue)
// 128x128 tile, BK=16, 256 threads, 8x8 microtile, double-buffered smem.
// Inner loop uses packed fma.rn.f32x2 (2 fp32 FMA per instruction).
// MODE 1: x = concat(points1, g_interp), C = g_y1
// MODE 2: x = relu(alpha1*g_y1 + beta1) fused at load, C = d_out (raw y2)
// ---------------------------------------------------------------------------
template <int MODE>
__global__ void __launch_bounds__(256) k_gemm(const float* __restrict__ A,
                                              const float* __restrict__ Bsrc,
                                              const float* __restrict__ bias,
                                              float* __restrict__ C, int K)
{
    __shared__ float As[2][16][128];
    __shared__ float Bs[2][16][128];

    const int tid = threadIdx.x;
    const int bb  = blockIdx.x >> 5;          // batch
    const int n0  = (blockIdx.x & 31) << 7;   // sample-tile origin within batch
    const int o0  = blockIdx.y << 7;          // output-channel tile origin
    const int tx  = tid & 15, ty = tid >> 4;

    unsigned long long acc[8][4];
#pragma unroll
    for (int i = 0; i < 8; i++)
#pragma unroll
        for (int j = 0; j < 4; j++) acc[i][j] = 0ULL;

    float4 ra[2], rb[2];

    auto g_load = [&](int k0) {
#pragma unroll
        for (int p = 0; p < 2; p++) {                 // A tile: 128 rows x 16 k
            int v = tid + (p << 8);
            int row = v >> 2, kq = (v & 3) << 2;
            ra[p] = *reinterpret_cast<const float4*>(A + (size_t)(o0 + row) * K + (k0 + kq));
        }
#pragma unroll
        for (int p = 0; p < 2; p++) {                 // B tile: 16 k x 128 samples
            int v = tid + (p << 8);
            int r = v >> 5, col = (v & 31) << 2;
            int c = k0 + r;
            float4 t;
            if (MODE == 1) {
                const float* src = (c < D1_)
                    ? (Bsrc     + ((size_t)bb * D1_ + c)        * NPT)
                    : (g_interp + ((size_t)bb * D2_ + (c - D1_)) * NPT);
                t = *reinterpret_cast<const float4*>(src + n0 + col);
            } else {
                const float* src = Bsrc + ((size_t)bb * CO + c) * NPT;
                t = *reinterpret_cast<const float4*>(src + n0 + col);
                const float al = g_alpha1[c], be = g_beta1[c];
                t.x = fmaxf(fmaf(al, t.x, be), 0.f);
                t.y = fmaxf(fmaf(al, t.y, be), 0.f);
                t.z = fmaxf(fmaf(al, t.z, be), 0.f);
                t.w = fmaxf(fmaf(al, t.w, be), 0.f);
            }
            rb[p] = t;
        }
    };

    auto s_store = [&](int buf) {
#pragma unroll
        for (int p = 0; p < 2; p++) {
            int v = tid + (p << 8);
            int row = v >> 2, kq = (v & 3) << 2;
            As[buf][kq + 0][row] = ra[p].x; As[buf][kq + 1][row] = ra[p].y;
            As[buf][kq + 2][row] = ra[p].z; As[buf][kq + 3][row] = ra[p].w;
        }
#pragma unroll
        for (int p = 0; p < 2; p++) {
            int v = tid + (p << 8);
            int r = v >> 5, col = (v & 31) << 2;
            *reinterpret_cast<float4*>(&Bs[buf][r][col]) = rb[p];
        }
    };

    const int KT = K >> 4;
    g_load(0);
    s_store(0);
    __syncthreads();

#pragma unroll 1
    for (int kt = 0; kt < KT; kt++) {
        const int buf = kt & 1;
        if (kt + 1 < KT) g_load((kt + 1) << 4);
#pragma unroll
        for (int k = 0; k < 16; k++) {
            const float4 a0 = *reinterpret_cast<const float4*>(&As[buf][k][ty << 2]);
            const float4 a1 = *reinterpret_cast<const float4*>(&As[buf][k][64 + (ty << 2)]);
            const ulonglong2 p0 = *reinterpret_cast<const ulonglong2*>(&Bs[buf][k][tx << 2]);
            const ulonglong2 p1 = *reinterpret_cast<const ulonglong2*>(&Bs[buf][k][64 + (tx << 2)]);
            const unsigned long long bv0 = p0.x, bv1 = p0.y, bv2 = p1.x, bv3 = p1.y;
            const float aa[8] = {a0.x, a0.y, a0.z, a0.w, a1.x, a1.y, a1.z, a1.w};
#pragma unroll
            for (int i = 0; i < 8; i++) {
                unsigned long long ap;
                asm("mov.b64 %0, {%1, %1};" : "=l"(ap) : "f"(aa[i]));
                asm("fma.rn.f32x2 %0, %1, %2, %0;" : "+l"(acc[i][0]) : "l"(ap), "l"(bv0));
                asm("fma.rn.f32x2 %0, %1, %2, %0;" : "+l"(acc[i][1]) : "l"(ap), "l"(bv1));
                asm("fma.rn.f32x2 %0, %1, %2, %0;" : "+l"(acc[i][2]) : "l"(ap), "l"(bv2));
                asm("fma.rn.f32x2 %0, %1, %2, %0;" : "+l"(acc[i][3]) : "l"(ap), "l"(bv3));
            }
        }
        if (kt + 1 < KT) { s_store((kt + 1) & 1); __syncthreads(); }
    }

    // ---- epilogue: unpack, add bias, vectorized store ----
#pragma unroll
    for (int i = 0; i < 8; i++) {
        const int o = o0 + ((i < 4) ? (ty << 2) + i : 64 + (ty << 2) + i - 4);
        const float bval = bias[o];
        float* dst = C + ((size_t)bb * CO + o) * NPT + n0;
        float x0, x1, x2, x3;
        asm("mov.b64 {%0, %1}, %2;" : "=f"(x0), "=f"(x1) : "l"(acc[i][0]));
        asm("mov.b64 {%0, %1}, %2;" : "=f"(x2), "=f"(x3) : "l"(acc[i][1]));
        float4 o4 = make_float4(x0 + bval, x1 + bval, x2 + bval, x3 + bval);
        *reinterpret_cast<float4*>(dst + (tx << 2)) = o4;
        asm("mov.b64 {%0, %1}, %2;" : "=f"(x0), "=f"(x1) : "l"(acc[i][2]));
        asm("mov.b64 {%0, %1}, %2;" : "=f"(x2), "=f"(x3) : "l"(acc[i][3]));
        float4 o5 = make_float4(x0 + bval, x1 + bval, x2 + bval, x3 + bval);
        *reinterpret_cast<float4*>(dst + 64 + (tx << 2)) = o5;
    }
}

// ---------------------------------------------------------------------------
// Kernel 4: per-channel BN stats (deterministic tree reduce) -> folded affine
// alpha = gamma * rsqrt(var + eps), beta' = beta - mean * alpha
// ---------------------------------------------------------------------------
__global__ void k_stats(const float* __restrict__ y, const float* __restrict__ gamma,
                        const float* __restrict__ beta, int layer)
{
    __shared__ float sh[256], sh2[256];
    const int c = blockIdx.x, tid = threadIdx.x;
    float s = 0.f, ss = 0.f;
    const float* base = y + (size_t)c * NPT;
    for (int i = tid; i < NS; i += 256) {
        const int b = i >> 12, n = i & 4095;
        const float v = base[(size_t)b * CO * NPT + n];
        s += v;
        ss = fmaf(v, v, ss);
    }
    sh[tid] = s; sh2[tid] = ss;
    __syncthreads();
    for (int off = 128; off > 0; off >>= 1) {
        if (tid < off) { sh[tid] += sh[tid + off]; sh2[tid] += sh2[tid + off]; }
        __syncthreads();
    }
    if (tid == 0) {
        const float mean = sh[0] * (1.f / (float)NS);
        const float var  = sh2[0] * (1.f / (float)NS) - mean * mean;
        const float a    = gamma[c] * rsqrtf(var + 1e-5f);
        const float bp   = beta[c] - mean * a;
        if (layer == 1) { g_alpha1[c] = a; g_beta1[c] = bp; }
        else            { g_alpha2[c] = a; g_beta2[c] = bp; }
    }
}

// ---------------------------------------------------------------------------
// Kernel 5: in-place finalize of d_out: out = relu(alpha2*y2 + beta2)
// ---------------------------------------------------------------------------
__global__ void k_finalize(float4* __restrict__ out)
{
    const int i = blockIdx.x * 256 + threadIdx.x;   // float4 index; 1024 per channel row
    float4 v = out[i];
    const int c = (i >> 10) & 255;
    const float a = g_alpha2[c], b = g_beta2[c];
    v.x = fmaxf(fmaf(a, v.x, b), 0.f);
    v.y = fmaxf(fmaf(a, v.y, b), 0.f);
    v.z = fmaxf(fmaf(a, v.z, b), 0.f);
    v.w = fmaxf(fmaf(a, v.w, b), 0.f);
    out[i] = v;
}

// ---------------------------------------------------------------------------
// Launch
// ---------------------------------------------------------------------------
extern "C" void kernel_launch(void* const* d_in, const int* in_sizes, int n_in,
                              void* d_out, int out_size)
{
    const float* xyz1    = (const float*)d_in[0];
    const float* xyz2    = (const float*)d_in[1];
    const float* points1 = (const float*)d_in[2];
    const float* points2 = (const float*)d_in[3];
    const float* W1      = (const float*)d_in[4];
    const float* b1      = (const float*)d_in[5];
    const float* g1      = (const float*)d_in[6];
    const float* be1     = (const float*)d_in[7];
    const float* W2      = (const float*)d_in[8];
    const float* b2      = (const float*)d_in[9];
    const float* g2      = (const float*)d_in[10];
    const float* be2     = (const float*)d_in[11];
    float* out = (float*)d_out;

    void* sym = nullptr;
    cudaGetSymbolAddress(&sym, g_y1);
    float* y1 = (float*)sym;

    cudaFuncSetAttribute(k_interp, cudaFuncAttributeMaxDynamicSharedMemorySize, INTERP_SMEM);

    k_transpose<<<dim3(32, 4, 16), dim3(32, 8)>>>(points2);
    k_interp<<<dim3(32, 16), 128, INTERP_SMEM>>>(xyz1, xyz2);
    k_gemm<1><<<dim3(512, 2), 256>>>(W1, points1, b1, y1, CIN);
    k_stats<<<256, 256>>>(y1, g1, be1, 1);
    k_gemm<2><<<dim3(512, 2), 256>>>(W2, y1, b2, out, CO);
    k_stats<<<256, 256>>>(out, g2, be2, 2);
    k_finalize<<<16384, 256>>>((float4*)out);
}